// round 2
// baseline (speedup 1.0000x reference)
#include <cuda_runtime.h>
#include <cuda_bf16.h>
#include <math.h>

// ---------------- problem constants (dataset is fixed) ----------------
#define NN 50000      // nodes
#define EE 600000     // edges
#define DH 128        // feature dim
#define GG 512        // graphs

// ---------------- device scratch (no allocation allowed) ----------------
__device__ float d_agg [NN * DH];
__device__ float d_hpre[NN * DH];
__device__ float d_h1  [NN * DH];
__device__ float d_h2  [NN * DH];
__device__ float d_pool[GG * 4 * DH];     // [G, 512] = a1|a2|m1|m2
__device__ float d_r1  [GG * 4 * DH];     // readout hidden [G, 512]
__device__ int   d_src [EE];
__device__ int   d_dst [EE];
__device__ int   d_batch[NN];
__device__ int   d_gstart[GG];
__device__ int   d_gend [GG];
__device__ int   d_deg   [NN];
__device__ int   d_rowptr[NN + 1];
__device__ int   d_cursor[NN];
__device__ int   d_csrc  [EE];            // CSR-by-dst: source node per in-edge
__device__ float d_colstats[4 * DH];      // conv1: sum|sumsq ; conv2: sum|sumsq
__device__ float d_scale[DH];
__device__ float d_shift[DH];
__device__ int   d_flag_edge;
__device__ int   d_flag_batch;

// ---------------- dtype detection (int64 vs int32 indices), parallel ------
__global__ void detect_k(const void* edge, const void* batch,
                         int e2cnt, int ncnt, long long nodeMax, long long gMax) {
    int tid = threadIdx.x;   // 256
    const long long* e64 = (const long long*)edge;
    const long long* b64 = (const long long*)batch;
    long long cnt = e2cnt / 2;   // only probe first half if data were int32
    long long idx = (cnt - 1) * (long long)tid / 255;
    long long v = e64[idx];
    int bad = (v < 0 || v >= nodeMax) ? 1 : 0;
    int anybad = __syncthreads_or(bad);
    if (tid == 0) d_flag_edge = !anybad;

    cnt = ncnt / 2;
    idx = (cnt - 1) * (long long)tid / 255;
    v = b64[idx];
    bad = (v < 0 || v >= gMax) ? 1 : 0;
    anybad = __syncthreads_or(bad);
    if (tid == 0) d_flag_batch = !anybad;
}

__global__ void convert_k(const void* edge, const void* batch, int Ecnt, int Ncnt) {
    int i = blockIdx.x * blockDim.x + threadIdx.x;
    int total = 2 * Ecnt + Ncnt;
    if (i >= total) return;
    int fe = d_flag_edge, fb = d_flag_batch;
    if (i < 2 * Ecnt) {
        long long v = fe ? ((const long long*)edge)[i]
                         : (long long)((const int*)edge)[i];
        if (i < Ecnt) d_src[i] = (int)v;
        else          d_dst[i - Ecnt] = (int)v;
    } else {
        int j = i - 2 * Ecnt;
        long long v = fb ? ((const long long*)batch)[j]
                         : (long long)((const int*)batch)[j];
        d_batch[j] = (int)v;
    }
}

// ---------------- segment bounds (batch is sorted) ----------------
__global__ void init_bounds_k(int Ncnt) {
    int g = blockIdx.x * blockDim.x + threadIdx.x;
    if (g < GG) { d_gstart[g] = Ncnt; d_gend[g] = 0; }
}
__global__ void fill_bounds_k(int Ncnt) {
    int i = blockIdx.x * blockDim.x + threadIdx.x;
    if (i >= Ncnt) return;
    int g = d_batch[i];
    atomicMin(&d_gstart[g], i);
    atomicMax(&d_gend[g], i + 1);
}

// ---------------- CSR-by-destination build ----------------
__global__ void zero_int_k(int* p, int n) {
    int i = blockIdx.x * blockDim.x + threadIdx.x;
    if (i < n) p[i] = 0;
}
__global__ void zero_f_k(float* p, int n) {
    int i = blockIdx.x * blockDim.x + threadIdx.x;
    if (i < n) p[i] = 0.0f;
}
__global__ void hist_k(int Ecnt) {
    int e = blockIdx.x * blockDim.x + threadIdx.x;
    if (e < Ecnt) atomicAdd(&d_deg[d_dst[e]], 1);
}
// single-block chunked exclusive scan of d_deg -> d_rowptr
__global__ void scan_k(int n) {
    __shared__ int sh[1024];
    __shared__ int base_s;
    int tid = threadIdx.x;
    if (tid == 0) base_s = 0;
    __syncthreads();
    for (int start = 0; start < n; start += 1024) {
        int i = start + tid;
        int v = (i < n) ? d_deg[i] : 0;
        sh[tid] = v;
        __syncthreads();
        #pragma unroll
        for (int off = 1; off < 1024; off <<= 1) {
            int t = (tid >= off) ? sh[tid - off] : 0;
            __syncthreads();
            sh[tid] += t;
            __syncthreads();
        }
        int b = base_s;
        if (i < n) d_rowptr[i] = b + sh[tid] - v;
        int tot = sh[1023];
        __syncthreads();
        if (tid == 0) base_s = b + tot;
        __syncthreads();
    }
    if (tid == 0) d_rowptr[n] = base_s;
}
__global__ void cursor_copy_k(int n) {
    int i = blockIdx.x * blockDim.x + threadIdx.x;
    if (i < n) d_cursor[i] = d_rowptr[i];
}
__global__ void fill_csr_k(int Ecnt) {
    int e = blockIdx.x * blockDim.x + threadIdx.x;
    if (e >= Ecnt) return;
    int pos = atomicAdd(&d_cursor[d_dst[e]], 1);
    d_csrc[pos] = d_src[e];
}

// ---------------- gather aggregation: agg[v] = x[v] + sum_{(u->v)} x[u] ----
__global__ void gather_k(const float* __restrict__ x, float* __restrict__ agg, int Ncnt) {
    int node = blockIdx.x * 8 + (threadIdx.x >> 5);
    int lane = threadIdx.x & 31;
    if (node >= Ncnt) return;
    int s = d_rowptr[node], e = d_rowptr[node + 1];
    float4 acc = *((const float4*)(x + (size_t)node * DH) + lane);   // self term
    for (int i = s; i < e; i++) {
        int src = d_csrc[i];
        float4 v = *((const float4*)(x + (size_t)src * DH) + lane);
        acc.x += v.x; acc.y += v.y; acc.z += v.z; acc.w += v.w;
    }
    *((float4*)(agg + (size_t)node * DH) + lane) = acc;
}

// ---------------- tiled SGEMM, BM=BN=128, BK=16, 256 threads, 8x8/thread ----
// MODE 0: epilogue: +bias, write C, accumulate column stats
// MODE 1: A := relu(scale[k]*A + shift[k]) on load, epilogue: relu(+bias)
// MODE 2: plain A, epilogue: relu(+bias)
template<int MODE>
__global__ __launch_bounds__(256)
void gemm_k(const float* __restrict__ A,
            const float* __restrict__ B, const float* __restrict__ bias,
            float* __restrict__ C, int M, int K, int NC,
            const float* __restrict__ scale, const float* __restrict__ shift,
            float* __restrict__ colstats)
{
    __shared__ float As[16][128];
    __shared__ float Bs[16][132];
    const int tid = threadIdx.x;
    const int row0 = blockIdx.x * 128;
    const int col0 = blockIdx.y * 128;
    const int tx = tid & 15;       // column group
    const int ty = tid >> 4;       // row group

    float acc[8][8];
    #pragma unroll
    for (int i = 0; i < 8; i++)
        #pragma unroll
        for (int j = 0; j < 8; j++) acc[i][j] = 0.0f;

    for (int k0 = 0; k0 < K; k0 += 16) {
        #pragma unroll
        for (int li = 0; li < 2; li++) {
            int e = tid * 2 + li;
            int r = e >> 2;
            int c = (e & 3) * 4;
            int grow = row0 + r;
            float4 v = make_float4(0.f, 0.f, 0.f, 0.f);
            if (grow < M) {
                v = *(const float4*)(A + (size_t)grow * K + k0 + c);
                if (MODE == 1) {
                    v.x = fmaxf(fmaf(scale[k0 + c + 0], v.x, shift[k0 + c + 0]), 0.f);
                    v.y = fmaxf(fmaf(scale[k0 + c + 1], v.y, shift[k0 + c + 1]), 0.f);
                    v.z = fmaxf(fmaf(scale[k0 + c + 2], v.z, shift[k0 + c + 2]), 0.f);
                    v.w = fmaxf(fmaf(scale[k0 + c + 3], v.w, shift[k0 + c + 3]), 0.f);
                }
            }
            As[c + 0][r] = v.x; As[c + 1][r] = v.y;
            As[c + 2][r] = v.z; As[c + 3][r] = v.w;
        }
        #pragma unroll
        for (int li = 0; li < 2; li++) {
            int e = tid * 2 + li;
            int br = e >> 5;
            int bc = (e & 31) * 4;
            float4 v = *(const float4*)(B + (size_t)(k0 + br) * NC + col0 + bc);
            *(float4*)&Bs[br][bc] = v;
        }
        __syncthreads();
        #pragma unroll
        for (int kk = 0; kk < 16; kk++) {
            float ra[8], rb[8];
            #pragma unroll
            for (int i = 0; i < 8; i++) ra[i] = As[kk][ty * 8 + i];
            #pragma unroll
            for (int j = 0; j < 8; j++) rb[j] = Bs[kk][tx * 8 + j];
            #pragma unroll
            for (int i = 0; i < 8; i++)
                #pragma unroll
                for (int j = 0; j < 8; j++)
                    acc[i][j] = fmaf(ra[i], rb[j], acc[i][j]);
        }
        __syncthreads();
    }

    #pragma unroll
    for (int j = 0; j < 8; j++) {
        int col = col0 + tx * 8 + j;
        float b = bias[col];
        float csum = 0.f, csq = 0.f;
        #pragma unroll
        for (int i = 0; i < 8; i++) {
            int row = row0 + ty * 8 + i;
            if (row < M) {
                float c = acc[i][j] + b;
                if (MODE == 1 || MODE == 2) c = fmaxf(c, 0.f);
                C[(size_t)row * NC + col] = c;
                if (MODE == 0) { csum += c; csq += c * c; }
            }
        }
        if (MODE == 0) {
            atomicAdd(&colstats[col], csum);
            atomicAdd(&colstats[DH + col], csq);
        }
    }
}

// ---------------- BN finalize ----------------
__global__ void bn_finalize_k(const float* __restrict__ g, const float* __restrict__ be,
                              int M, int statoff) {
    int j = threadIdx.x;
    if (j >= DH) return;
    float mu = d_colstats[statoff + j] / (float)M;
    float var = d_colstats[statoff + DH + j] / (float)M - mu * mu;
    float sc = g[j] * rsqrtf(var + 1e-5f);
    d_scale[j] = sc;
    d_shift[j] = be[j] - mu * sc;
}

// ---------------- pooling: one block per graph ----------------
__global__ void pool_k(const float* __restrict__ h, int off_sum, int off_max) {
    int gph = blockIdx.x;
    int j = threadIdx.x;   // 128
    int s = d_gstart[gph], e = d_gend[gph];
    float sum = 0.f, mx = 0.f;
    int r = s;
    for (; r + 4 <= e; r += 4) {
        float v0 = h[(size_t)(r + 0) * DH + j];
        float v1 = h[(size_t)(r + 1) * DH + j];
        float v2 = h[(size_t)(r + 2) * DH + j];
        float v3 = h[(size_t)(r + 3) * DH + j];
        sum += v0 + v1 + v2 + v3;
        mx = fmaxf(mx, fmaxf(fmaxf(v0, v1), fmaxf(v2, v3)));
    }
    for (; r < e; r++) {
        float v = h[(size_t)r * DH + j];
        sum += v; mx = fmaxf(mx, v);
    }
    d_pool[(size_t)gph * 512 + off_sum + j] = sum;
    d_pool[(size_t)gph * 512 + off_max + j] = mx;
}

// ---------------- final linear + sigmoid ----------------
__global__ void final_k(const float* __restrict__ r1, const float* __restrict__ w,
                        const float* __restrict__ b, float* __restrict__ out, int out_size) {
    int gph = blockIdx.x;
    int tid = threadIdx.x;   // 128
    float s = 0.f;
    #pragma unroll
    for (int k = tid; k < 512; k += 128) s += r1[(size_t)gph * 512 + k] * w[k];
    __shared__ float red[128];
    red[tid] = s;
    __syncthreads();
    for (int st = 64; st > 0; st >>= 1) {
        if (tid < st) red[tid] += red[tid + st];
        __syncthreads();
    }
    if (tid == 0) {
        float h = red[0] + b[0];
        float sg = 1.f / (1.f + expf(-h));
        out[gph] = sg;
        if (out_size >= 2 * GG) out[GG + gph] = h;
    }
}

// ---------------- host launch ----------------
extern "C" void kernel_launch(void* const* d_in, const int* in_sizes, int n_in,
                              void* d_out, int out_size) {
    const float* x      = (const float*)d_in[0];
    const void*  edge   = d_in[1];
    const void*  batch  = d_in[2];
    const float* c1_W1  = (const float*)d_in[3];
    const float* c1_b1  = (const float*)d_in[4];
    const float* c1_g   = (const float*)d_in[5];
    const float* c1_be  = (const float*)d_in[6];
    const float* c1_W2  = (const float*)d_in[7];
    const float* c1_b2  = (const float*)d_in[8];
    const float* c2_W1  = (const float*)d_in[9];
    const float* c2_b1  = (const float*)d_in[10];
    const float* c2_g   = (const float*)d_in[11];
    const float* c2_be  = (const float*)d_in[12];
    const float* c2_W2  = (const float*)d_in[13];
    const float* c2_b2  = (const float*)d_in[14];
    const float* lin1_W = (const float*)d_in[15];
    const float* lin1_b = (const float*)d_in[16];
    const float* lin2_W = (const float*)d_in[17];
    const float* lin2_b = (const float*)d_in[18];

    const int N = in_sizes[0] / DH;       // 50000
    const int E = in_sizes[1] / 2;        // 600000
    float* out = (float*)d_out;

    float *agg, *hpre, *h1, *h2, *pool, *r1, *colstats, *sc, *sh;
    int *deg, *cursor;
    cudaGetSymbolAddress((void**)&agg,      d_agg);
    cudaGetSymbolAddress((void**)&hpre,     d_hpre);
    cudaGetSymbolAddress((void**)&h1,       d_h1);
    cudaGetSymbolAddress((void**)&h2,       d_h2);
    cudaGetSymbolAddress((void**)&pool,     d_pool);
    cudaGetSymbolAddress((void**)&r1,       d_r1);
    cudaGetSymbolAddress((void**)&colstats, d_colstats);
    cudaGetSymbolAddress((void**)&sc,       d_scale);
    cudaGetSymbolAddress((void**)&sh,       d_shift);
    cudaGetSymbolAddress((void**)&deg,      d_deg);
    cudaGetSymbolAddress((void**)&cursor,   d_cursor);

    // 1) index dtype detection + conversion
    detect_k<<<1, 256>>>(edge, batch, 2 * E, N, (long long)N, (long long)GG);
    convert_k<<<(2 * E + N + 255) / 256, 256>>>(edge, batch, E, N);

    // 2) per-graph segment bounds (batch sorted)
    init_bounds_k<<<(GG + 255) / 256, 256>>>(N);
    fill_bounds_k<<<(N + 255) / 256, 256>>>(N);

    // 3) CSR-by-destination build
    zero_int_k<<<(N + 255) / 256, 256>>>(deg, N);
    hist_k<<<(E + 255) / 256, 256>>>(E);
    scan_k<<<1, 1024>>>(N);
    cursor_copy_k<<<(N + 255) / 256, 256>>>(N);
    fill_csr_k<<<(E + 255) / 256, 256>>>(E);

    // 4) zero both colstats buffers
    zero_f_k<<<2, 256>>>(colstats, 4 * DH);

    const int gemm_gx = (N + 127) / 128;
    const dim3 gemm_grid(gemm_gx, 1);
    const int gather_blocks = (N + 7) / 8;

    // ---- conv1 ----
    gather_k<<<gather_blocks, 256>>>(x, agg, N);
    gemm_k<0><<<gemm_grid, 256>>>(agg, c1_W1, c1_b1, hpre, N, DH, DH,
                                  nullptr, nullptr, colstats);
    bn_finalize_k<<<1, DH>>>(c1_g, c1_be, N, 0);
    gemm_k<1><<<gemm_grid, 256>>>(hpre, c1_W2, c1_b2, h1, N, DH, DH,
                                  sc, sh, nullptr);
    pool_k<<<GG, DH>>>(h1, 0, 256);

    // ---- conv2 ----
    gather_k<<<gather_blocks, 256>>>(h1, agg, N);
    gemm_k<0><<<gemm_grid, 256>>>(agg, c2_W1, c2_b1, hpre, N, DH, DH,
                                  nullptr, nullptr, colstats + 2 * DH);
    bn_finalize_k<<<1, DH>>>(c2_g, c2_be, N, 2 * DH);
    gemm_k<1><<<gemm_grid, 256>>>(hpre, c2_W2, c2_b2, h2, N, DH, DH,
                                  sc, sh, nullptr);
    pool_k<<<GG, DH>>>(h2, 128, 384);

    // ---- readout ----
    {
        dim3 grid((GG + 127) / 128, 4);   // M=512, NC=512
        gemm_k<2><<<grid, 256>>>(pool, lin1_W, lin1_b, r1, GG, 512, 512,
                                 nullptr, nullptr, nullptr);
    }
    final_k<<<GG, 128>>>(r1, lin2_W, lin2_b, out, out_size);
}

// round 3
// speedup vs baseline: 1.4389x; 1.4389x over previous
#include <cuda_runtime.h>
#include <cuda_bf16.h>
#include <math.h>

// ---------------- problem constants (dataset is fixed) ----------------
#define NN 50000      // nodes
#define EE 600000     // edges
#define DH 128        // feature dim
#define GG 512        // graphs

// ---------------- device scratch (no allocation allowed) ----------------
__device__ float d_agg [NN * DH];
__device__ float d_hpre[NN * DH];
__device__ float d_h1  [NN * DH];
__device__ float d_h2  [NN * DH];
__device__ float d_pool[GG * 4 * DH];     // [G, 512] = a1|a2|m1|m2
__device__ float d_r1  [GG * 4 * DH];     // readout hidden [G, 512]
__device__ int   d_src [EE];
__device__ int   d_dst [EE];
__device__ int   d_batch[NN];
__device__ int   d_gstart[GG];
__device__ int   d_gend [GG];
__device__ float d_colstats[4 * DH];      // conv1: sum|sumsq ; conv2: sum|sumsq
__device__ float d_scale[DH];
__device__ float d_shift[DH];
__device__ int   d_flag_edge;
__device__ int   d_flag_batch;

// ---------------- dtype detection (int64 vs int32 indices), parallel ------
__global__ void detect_k(const void* edge, const void* batch,
                         int e2cnt, int ncnt, long long nodeMax, long long gMax) {
    int tid = threadIdx.x;   // 256
    const long long* e64 = (const long long*)edge;
    const long long* b64 = (const long long*)batch;
    long long cnt = e2cnt / 2;   // only probe first half if data were int32
    long long idx = (cnt - 1) * (long long)tid / 255;
    long long v = e64[idx];
    int bad = (v < 0 || v >= nodeMax) ? 1 : 0;
    int anybad = __syncthreads_or(bad);
    if (tid == 0) d_flag_edge = !anybad;

    cnt = ncnt / 2;
    idx = (cnt - 1) * (long long)tid / 255;
    v = b64[idx];
    bad = (v < 0 || v >= gMax) ? 1 : 0;
    anybad = __syncthreads_or(bad);
    if (tid == 0) d_flag_batch = !anybad;
}

__global__ void convert_k(const void* edge, const void* batch, int Ecnt, int Ncnt) {
    int i = blockIdx.x * blockDim.x + threadIdx.x;
    int total = 2 * Ecnt + Ncnt;
    if (i >= total) return;
    int fe = d_flag_edge, fb = d_flag_batch;
    if (i < 2 * Ecnt) {
        long long v = fe ? ((const long long*)edge)[i]
                         : (long long)((const int*)edge)[i];
        if (i < Ecnt) d_src[i] = (int)v;
        else          d_dst[i - Ecnt] = (int)v;
    } else {
        int j = i - 2 * Ecnt;
        long long v = fb ? ((const long long*)batch)[j]
                         : (long long)((const int*)batch)[j];
        d_batch[j] = (int)v;
    }
}

// ---------------- segment bounds via binary search (batch is sorted) -------
__global__ void bounds_k(int Ncnt) {
    int g = blockIdx.x * blockDim.x + threadIdx.x;
    if (g >= GG) return;
    int lo = 0, hi = Ncnt;
    while (lo < hi) { int mid = (lo + hi) >> 1; if (d_batch[mid] < g) lo = mid + 1; else hi = mid; }
    d_gstart[g] = lo;
    lo = 0; hi = Ncnt;
    while (lo < hi) { int mid = (lo + hi) >> 1; if (d_batch[mid] < g + 1) lo = mid + 1; else hi = mid; }
    d_gend[g] = lo;
}

// ---------------- zero fill (float4, grid-stride) ----------------
__global__ void zero_k(float* p, int n4) {
    int i = blockIdx.x * blockDim.x + threadIdx.x;
    int stride = gridDim.x * blockDim.x;
    float4 z = make_float4(0.f, 0.f, 0.f, 0.f);
    for (; i < n4; i += stride) ((float4*)p)[i] = z;
}

// ---------------- edge scatter: agg[dst] += x[src], v4 reductions ----------
__global__ void scatter_k(const float* __restrict__ x, float* __restrict__ agg, int Ecnt) {
    int t = blockIdx.x * blockDim.x + threadIdx.x;
    int e = t >> 5, lane = t & 31;
    if (e >= Ecnt) return;
    int s = d_src[e], d = d_dst[e];
    float4 v = *((const float4*)(x + (size_t)s * DH) + lane);
    float4* p = (float4*)(agg + (size_t)d * DH) + lane;
    asm volatile("red.global.add.v4.f32 [%0], {%1,%2,%3,%4};"
                 :: "l"(p), "f"(v.x), "f"(v.y), "f"(v.z), "f"(v.w) : "memory");
}

// ---------------- tiled SGEMM, BM=BN=128, BK=16, 256 threads, 8x8/thread ----
// MODE 0: A := A + A2 (elementwise), epilogue: +bias, write C, column stats
// MODE 1: A := relu(scale[k]*A + shift[k]) on load, epilogue: relu(+bias)
// MODE 2: plain A, epilogue: relu(+bias)
template<int MODE>
__global__ __launch_bounds__(256)
void gemm_k(const float* __restrict__ A, const float* __restrict__ A2,
            const float* __restrict__ B, const float* __restrict__ bias,
            float* __restrict__ C, int M, int K, int NC,
            const float* __restrict__ scale, const float* __restrict__ shift,
            float* __restrict__ colstats)
{
    __shared__ float As[16][128];
    __shared__ float Bs[16][132];
    const int tid = threadIdx.x;
    const int row0 = blockIdx.x * 128;
    const int col0 = blockIdx.y * 128;
    const int tx = tid & 15;       // column group
    const int ty = tid >> 4;       // row group

    float acc[8][8];
    #pragma unroll
    for (int i = 0; i < 8; i++)
        #pragma unroll
        for (int j = 0; j < 8; j++) acc[i][j] = 0.0f;

    for (int k0 = 0; k0 < K; k0 += 16) {
        #pragma unroll
        for (int li = 0; li < 2; li++) {
            int e = tid * 2 + li;
            int r = e >> 2;
            int c = (e & 3) * 4;
            int grow = row0 + r;
            float4 v = make_float4(0.f, 0.f, 0.f, 0.f);
            if (grow < M) {
                v = *(const float4*)(A + (size_t)grow * K + k0 + c);
                if (MODE == 0) {
                    float4 u = *(const float4*)(A2 + (size_t)grow * K + k0 + c);
                    v.x += u.x; v.y += u.y; v.z += u.z; v.w += u.w;
                }
                if (MODE == 1) {
                    v.x = fmaxf(fmaf(scale[k0 + c + 0], v.x, shift[k0 + c + 0]), 0.f);
                    v.y = fmaxf(fmaf(scale[k0 + c + 1], v.y, shift[k0 + c + 1]), 0.f);
                    v.z = fmaxf(fmaf(scale[k0 + c + 2], v.z, shift[k0 + c + 2]), 0.f);
                    v.w = fmaxf(fmaf(scale[k0 + c + 3], v.w, shift[k0 + c + 3]), 0.f);
                }
            }
            As[c + 0][r] = v.x; As[c + 1][r] = v.y;
            As[c + 2][r] = v.z; As[c + 3][r] = v.w;
        }
        #pragma unroll
        for (int li = 0; li < 2; li++) {
            int e = tid * 2 + li;
            int br = e >> 5;
            int bc = (e & 31) * 4;
            float4 v = *(const float4*)(B + (size_t)(k0 + br) * NC + col0 + bc);
            *(float4*)&Bs[br][bc] = v;
        }
        __syncthreads();
        #pragma unroll
        for (int kk = 0; kk < 16; kk++) {
            float ra[8], rb[8];
            #pragma unroll
            for (int i = 0; i < 8; i++) ra[i] = As[kk][ty * 8 + i];
            #pragma unroll
            for (int j = 0; j < 8; j++) rb[j] = Bs[kk][tx * 8 + j];
            #pragma unroll
            for (int i = 0; i < 8; i++)
                #pragma unroll
                for (int j = 0; j < 8; j++)
                    acc[i][j] = fmaf(ra[i], rb[j], acc[i][j]);
        }
        __syncthreads();
    }

    #pragma unroll
    for (int j = 0; j < 8; j++) {
        int col = col0 + tx * 8 + j;
        float b = bias[col];
        float csum = 0.f, csq = 0.f;
        #pragma unroll
        for (int i = 0; i < 8; i++) {
            int row = row0 + ty * 8 + i;
            if (row < M) {
                float c = acc[i][j] + b;
                if (MODE == 1 || MODE == 2) c = fmaxf(c, 0.f);
                C[(size_t)row * NC + col] = c;
                if (MODE == 0) { csum += c; csq += c * c; }
            }
        }
        if (MODE == 0) {
            atomicAdd(&colstats[col], csum);
            atomicAdd(&colstats[DH + col], csq);
        }
    }
}

// ---------------- BN finalize ----------------
__global__ void bn_finalize_k(const float* __restrict__ g, const float* __restrict__ be,
                              int M, int statoff) {
    int j = threadIdx.x;
    if (j >= DH) return;
    float mu = d_colstats[statoff + j] / (float)M;
    float var = d_colstats[statoff + DH + j] / (float)M - mu * mu;
    float sc = g[j] * rsqrtf(var + 1e-5f);
    d_scale[j] = sc;
    d_shift[j] = be[j] - mu * sc;
}

// ---------------- pooling: one block (512 thr) per graph, 4-way rows -------
__global__ void pool_k(const float* __restrict__ h, int off_sum, int off_max) {
    __shared__ float ssum[4][128];
    __shared__ float smax[4][128];
    int gph = blockIdx.x;
    int j = threadIdx.x & 127;
    int part = threadIdx.x >> 7;   // 0..3
    int s = d_gstart[gph], e = d_gend[gph];
    float sum = 0.f, mx = 0.f;
    for (int r = s + part; r < e; r += 4) {
        float v = h[(size_t)r * DH + j];
        sum += v; mx = fmaxf(mx, v);
    }
    ssum[part][j] = sum;
    smax[part][j] = mx;
    __syncthreads();
    if (part == 0) {
        sum = ssum[0][j] + ssum[1][j] + ssum[2][j] + ssum[3][j];
        mx = fmaxf(fmaxf(smax[0][j], smax[1][j]), fmaxf(smax[2][j], smax[3][j]));
        // h is post-ReLU (>=0); empty segments -> 0 matches reference fixup
        d_pool[(size_t)gph * 512 + off_sum + j] = sum;
        d_pool[(size_t)gph * 512 + off_max + j] = mx;
    }
}

// ---------------- final linear + sigmoid ----------------
__global__ void final_k(const float* __restrict__ r1, const float* __restrict__ w,
                        const float* __restrict__ b, float* __restrict__ out, int out_size) {
    int gph = blockIdx.x;
    int tid = threadIdx.x;   // 128
    float s = 0.f;
    #pragma unroll
    for (int k = tid; k < 512; k += 128) s += r1[(size_t)gph * 512 + k] * w[k];
    __shared__ float red[128];
    red[tid] = s;
    __syncthreads();
    for (int st = 64; st > 0; st >>= 1) {
        if (tid < st) red[tid] += red[tid + st];
        __syncthreads();
    }
    if (tid == 0) {
        float h = red[0] + b[0];
        float sg = 1.f / (1.f + expf(-h));
        out[gph] = sg;
        if (out_size >= 2 * GG) out[GG + gph] = h;
    }
}

// ---------------- host launch ----------------
extern "C" void kernel_launch(void* const* d_in, const int* in_sizes, int n_in,
                              void* d_out, int out_size) {
    const float* x      = (const float*)d_in[0];
    const void*  edge   = d_in[1];
    const void*  batch  = d_in[2];
    const float* c1_W1  = (const float*)d_in[3];
    const float* c1_b1  = (const float*)d_in[4];
    const float* c1_g   = (const float*)d_in[5];
    const float* c1_be  = (const float*)d_in[6];
    const float* c1_W2  = (const float*)d_in[7];
    const float* c1_b2  = (const float*)d_in[8];
    const float* c2_W1  = (const float*)d_in[9];
    const float* c2_b1  = (const float*)d_in[10];
    const float* c2_g   = (const float*)d_in[11];
    const float* c2_be  = (const float*)d_in[12];
    const float* c2_W2  = (const float*)d_in[13];
    const float* c2_b2  = (const float*)d_in[14];
    const float* lin1_W = (const float*)d_in[15];
    const float* lin1_b = (const float*)d_in[16];
    const float* lin2_W = (const float*)d_in[17];
    const float* lin2_b = (const float*)d_in[18];

    const int N = in_sizes[0] / DH;       // 50000
    const int E = in_sizes[1] / 2;        // 600000
    float* out = (float*)d_out;

    float *agg, *hpre, *h1, *h2, *pool, *r1, *colstats, *sc, *sh;
    cudaGetSymbolAddress((void**)&agg,      d_agg);
    cudaGetSymbolAddress((void**)&hpre,     d_hpre);
    cudaGetSymbolAddress((void**)&h1,       d_h1);
    cudaGetSymbolAddress((void**)&h2,       d_h2);
    cudaGetSymbolAddress((void**)&pool,     d_pool);
    cudaGetSymbolAddress((void**)&r1,       d_r1);
    cudaGetSymbolAddress((void**)&colstats, d_colstats);
    cudaGetSymbolAddress((void**)&sc,       d_scale);
    cudaGetSymbolAddress((void**)&sh,       d_shift);

    // 1) index dtype detection + conversion
    detect_k<<<1, 256>>>(edge, batch, 2 * E, N, (long long)N, (long long)GG);
    convert_k<<<(2 * E + N + 255) / 256, 256>>>(edge, batch, E, N);

    // 2) per-graph segment bounds (batch sorted) via binary search
    bounds_k<<<2, 256>>>(N);

    // 3) zero colstats (both convs' buffers at once)
    zero_k<<<1, 128>>>(colstats, DH);   // 4*DH floats = DH float4s

    const int gemm_gx = (N + 127) / 128;
    const dim3 gemm_grid(gemm_gx, 1);
    const int scat_blocks = (E * 32 + 255) / 256;

    // ---- conv1 ----
    zero_k<<<1024, 256>>>(agg, N * DH / 4);
    scatter_k<<<scat_blocks, 256>>>(x, agg, E);
    gemm_k<0><<<gemm_grid, 256>>>(agg, x, c1_W1, c1_b1, hpre, N, DH, DH,
                                  nullptr, nullptr, colstats);
    bn_finalize_k<<<1, DH>>>(c1_g, c1_be, N, 0);
    gemm_k<1><<<gemm_grid, 256>>>(hpre, nullptr, c1_W2, c1_b2, h1, N, DH, DH,
                                  sc, sh, nullptr);
    pool_k<<<GG, 512>>>(h1, 0, 256);

    // ---- conv2 ----
    zero_k<<<1024, 256>>>(agg, N * DH / 4);
    scatter_k<<<scat_blocks, 256>>>(h1, agg, E);
    gemm_k<0><<<gemm_grid, 256>>>(agg, h1, c2_W1, c2_b1, hpre, N, DH, DH,
                                  nullptr, nullptr, colstats + 2 * DH);
    bn_finalize_k<<<1, DH>>>(c2_g, c2_be, N, 2 * DH);
    gemm_k<1><<<gemm_grid, 256>>>(hpre, nullptr, c2_W2, c2_b2, h2, N, DH, DH,
                                  sc, sh, nullptr);
    pool_k<<<GG, 512>>>(h2, 128, 384);

    // ---- readout ----
    {
        dim3 grid((GG + 127) / 128, 4);   // M=512, NC=512
        gemm_k<2><<<grid, 256>>>(pool, nullptr, lin1_W, lin1_b, r1, GG, 512, 512,
                                 nullptr, nullptr, nullptr);
    }
    final_k<<<GG, 128>>>(r1, lin2_W, lin2_b, out, out_size);
}

// round 4
// speedup vs baseline: 3.4498x; 2.3975x over previous
#include <cuda_runtime.h>
#include <cuda_bf16.h>
#include <math.h>
#include <stdint.h>

// ---------------- problem constants (dataset is fixed) ----------------
#define NN 50000      // nodes
#define EE 600000     // edges
#define DH 128        // feature dim
#define GG 512        // graphs

// ---------------- device scratch (no allocation allowed) ----------------
__device__ float d_agg [NN * DH];
__device__ float d_hpre[NN * DH];
__device__ float d_h1  [NN * DH];
__device__ float d_h2  [NN * DH];
__device__ float d_pool[GG * 4 * DH];     // [G, 512] = a1|a2|m1|m2
__device__ float d_r1  [GG * 4 * DH];     // readout hidden [G, 512]
__device__ int   d_src [EE];
__device__ int   d_dst [EE];
__device__ int   d_batch[NN];
__device__ int   d_gstart[GG];
__device__ int   d_gend [GG];
__device__ float d_colstats[4 * DH];      // conv1: sum|sumsq ; conv2: sum|sumsq
__device__ float d_scale[DH];
__device__ float d_shift[DH];
__device__ int   d_flag_edge;
__device__ int   d_flag_batch;

// ---------------- dtype detection (int64 vs int32 indices), parallel ------
__global__ void detect_k(const void* edge, const void* batch,
                         int e2cnt, int ncnt, long long nodeMax, long long gMax) {
    int tid = threadIdx.x;   // 256
    const long long* e64 = (const long long*)edge;
    const long long* b64 = (const long long*)batch;
    long long cnt = e2cnt / 2;   // only probe first half if data were int32
    long long idx = (cnt - 1) * (long long)tid / 255;
    long long v = e64[idx];
    int bad = (v < 0 || v >= nodeMax) ? 1 : 0;
    int anybad = __syncthreads_or(bad);
    if (tid == 0) d_flag_edge = !anybad;

    cnt = ncnt / 2;
    idx = (cnt - 1) * (long long)tid / 255;
    v = b64[idx];
    bad = (v < 0 || v >= gMax) ? 1 : 0;
    anybad = __syncthreads_or(bad);
    if (tid == 0) d_flag_batch = !anybad;
}

__global__ void convert_k(const void* edge, const void* batch, int Ecnt, int Ncnt) {
    int i = blockIdx.x * blockDim.x + threadIdx.x;
    int total = 2 * Ecnt + Ncnt;
    if (i >= total) return;
    int fe = d_flag_edge, fb = d_flag_batch;
    if (i < 2 * Ecnt) {
        long long v = fe ? ((const long long*)edge)[i]
                         : (long long)((const int*)edge)[i];
        if (i < Ecnt) d_src[i] = (int)v;
        else          d_dst[i - Ecnt] = (int)v;
    } else {
        int j = i - 2 * Ecnt;
        long long v = fb ? ((const long long*)batch)[j]
                         : (long long)((const int*)batch)[j];
        d_batch[j] = (int)v;
    }
}

// ---------------- segment bounds via binary search (batch is sorted) -------
__global__ void bounds_k(int Ncnt) {
    int g = blockIdx.x * blockDim.x + threadIdx.x;
    if (g >= GG) return;
    int lo = 0, hi = Ncnt;
    while (lo < hi) { int mid = (lo + hi) >> 1; if (d_batch[mid] < g) lo = mid + 1; else hi = mid; }
    d_gstart[g] = lo;
    lo = 0; hi = Ncnt;
    while (lo < hi) { int mid = (lo + hi) >> 1; if (d_batch[mid] < g + 1) lo = mid + 1; else hi = mid; }
    d_gend[g] = lo;
}

// ---------------- zero fill (float4, grid-stride) ----------------
__global__ void zero_k(float* p, int n4) {
    int i = blockIdx.x * blockDim.x + threadIdx.x;
    int stride = gridDim.x * blockDim.x;
    float4 z = make_float4(0.f, 0.f, 0.f, 0.f);
    for (; i < n4; i += stride) ((float4*)p)[i] = z;
}

// ---------------- edge scatter: agg[dst] += x[src], v4 reductions ----------
__global__ void scatter_k(const float* __restrict__ x, float* __restrict__ agg, int Ecnt) {
    int t = blockIdx.x * blockDim.x + threadIdx.x;
    int e = t >> 5, lane = t & 31;
    if (e >= Ecnt) return;
    int s = d_src[e], d = d_dst[e];
    float4 v = *((const float4*)(x + (size_t)s * DH) + lane);
    float4* p = (float4*)(agg + (size_t)d * DH) + lane;
    asm volatile("red.global.add.v4.f32 [%0], {%1,%2,%3,%4};"
                 :: "l"(p), "f"(v.x), "f"(v.y), "f"(v.z), "f"(v.w) : "memory");
}

// ---------------- 3xTF32 tensor-core GEMM -----------------------
// BM=BN=128, BK=16, 256 threads = 8 warps (2 x 4), warp tile 64x32.
// MODE 0: A := A + A2 on load, epilogue: +bias, write C, column stats
// MODE 1: A := relu(scale[k]*A + shift[k]) on load, epilogue: relu(+bias)
// MODE 2: plain A, epilogue: relu(+bias)
__device__ __forceinline__ uint32_t f2tf32(float x) {
    uint32_t r;
    asm("cvt.rna.tf32.f32 %0, %1;" : "=r"(r) : "f"(x));
    return r;
}
__device__ __forceinline__ void mma_tf32(float* c, uint32_t a0, uint32_t a1,
                                         uint32_t a2, uint32_t a3,
                                         uint32_t b0, uint32_t b1) {
    asm volatile("mma.sync.aligned.m16n8k8.row.col.f32.tf32.tf32.f32 "
                 "{%0,%1,%2,%3}, {%4,%5,%6,%7}, {%8,%9}, {%0,%1,%2,%3};"
                 : "+f"(c[0]), "+f"(c[1]), "+f"(c[2]), "+f"(c[3])
                 : "r"(a0), "r"(a1), "r"(a2), "r"(a3), "r"(b0), "r"(b1));
}

template<int MODE>
__global__ __launch_bounds__(256)
void gemm_tc(const float* __restrict__ A, const float* __restrict__ A2,
             const float* __restrict__ B, const float* __restrict__ bias,
             float* __restrict__ C, int M, int K, int NC,
             const float* __restrict__ scale, const float* __restrict__ shift,
             float* __restrict__ colstats)
{
    __shared__ __align__(16) float Ah[128][20];
    __shared__ __align__(16) float Al[128][20];
    __shared__ __align__(16) float Bh[16][136];
    __shared__ __align__(16) float Bl[16][136];

    const int tid  = threadIdx.x;
    const int lane = tid & 31;
    const int wid  = tid >> 5;
    const int wm   = wid & 1;          // warp row (0..1) -> 64 rows each
    const int wn   = wid >> 1;         // warp col (0..3) -> 32 cols each
    const int grp  = lane >> 2;
    const int quad = lane & 3;
    const int row0 = blockIdx.x * 128;
    const int col0 = blockIdx.y * 128;

    float acc[4][4][4];
    #pragma unroll
    for (int mf = 0; mf < 4; mf++)
        #pragma unroll
        for (int nf = 0; nf < 4; nf++)
            #pragma unroll
            for (int q = 0; q < 4; q++) acc[mf][nf][q] = 0.0f;

    for (int k0 = 0; k0 < K; k0 += 16) {
        // ---- load A tile (128 x 16) ----
        #pragma unroll
        for (int li = 0; li < 2; li++) {
            int f = li * 256 + tid;
            int r = f >> 2, c = (f & 3) * 4;
            int grow = row0 + r;
            float4 v = make_float4(0.f, 0.f, 0.f, 0.f);
            if (grow < M) {
                v = *(const float4*)(A + (size_t)grow * K + k0 + c);
                if (MODE == 0) {
                    float4 u = *(const float4*)(A2 + (size_t)grow * K + k0 + c);
                    v.x += u.x; v.y += u.y; v.z += u.z; v.w += u.w;
                }
                if (MODE == 1) {
                    v.x = fmaxf(fmaf(scale[k0 + c + 0], v.x, shift[k0 + c + 0]), 0.f);
                    v.y = fmaxf(fmaf(scale[k0 + c + 1], v.y, shift[k0 + c + 1]), 0.f);
                    v.z = fmaxf(fmaf(scale[k0 + c + 2], v.z, shift[k0 + c + 2]), 0.f);
                    v.w = fmaxf(fmaf(scale[k0 + c + 3], v.w, shift[k0 + c + 3]), 0.f);
                }
            }
            uint32_t hx = f2tf32(v.x), hy = f2tf32(v.y), hz = f2tf32(v.z), hw = f2tf32(v.w);
            float4 hi = make_float4(__uint_as_float(hx), __uint_as_float(hy),
                                    __uint_as_float(hz), __uint_as_float(hw));
            float4 lo;
            lo.x = __uint_as_float(f2tf32(v.x - hi.x));
            lo.y = __uint_as_float(f2tf32(v.y - hi.y));
            lo.z = __uint_as_float(f2tf32(v.z - hi.z));
            lo.w = __uint_as_float(f2tf32(v.w - hi.w));
            *(float4*)&Ah[r][c] = hi;
            *(float4*)&Al[r][c] = lo;
        }
        // ---- load B tile (16 x 128) ----
        #pragma unroll
        for (int li = 0; li < 2; li++) {
            int f = li * 256 + tid;
            int r = f >> 5, c = (f & 31) * 4;
            float4 v = *(const float4*)(B + (size_t)(k0 + r) * NC + col0 + c);
            uint32_t hx = f2tf32(v.x), hy = f2tf32(v.y), hz = f2tf32(v.z), hw = f2tf32(v.w);
            float4 hi = make_float4(__uint_as_float(hx), __uint_as_float(hy),
                                    __uint_as_float(hz), __uint_as_float(hw));
            float4 lo;
            lo.x = __uint_as_float(f2tf32(v.x - hi.x));
            lo.y = __uint_as_float(f2tf32(v.y - hi.y));
            lo.z = __uint_as_float(f2tf32(v.z - hi.z));
            lo.w = __uint_as_float(f2tf32(v.w - hi.w));
            *(float4*)&Bh[r][c] = hi;
            *(float4*)&Bl[r][c] = lo;
        }
        __syncthreads();

        #pragma unroll
        for (int ks = 0; ks < 2; ks++) {
            int k8 = ks * 8;
            uint32_t ah[4][4], al[4][4], bh[4][2], bl[4][2];
            #pragma unroll
            for (int mf = 0; mf < 4; mf++) {
                int rA = wm * 64 + mf * 16 + grp;
                ah[mf][0] = __float_as_uint(Ah[rA    ][k8 + quad    ]);
                ah[mf][1] = __float_as_uint(Ah[rA + 8][k8 + quad    ]);
                ah[mf][2] = __float_as_uint(Ah[rA    ][k8 + quad + 4]);
                ah[mf][3] = __float_as_uint(Ah[rA + 8][k8 + quad + 4]);
                al[mf][0] = __float_as_uint(Al[rA    ][k8 + quad    ]);
                al[mf][1] = __float_as_uint(Al[rA + 8][k8 + quad    ]);
                al[mf][2] = __float_as_uint(Al[rA    ][k8 + quad + 4]);
                al[mf][3] = __float_as_uint(Al[rA + 8][k8 + quad + 4]);
            }
            #pragma unroll
            for (int nf = 0; nf < 4; nf++) {
                int cB = wn * 32 + nf * 8 + grp;
                bh[nf][0] = __float_as_uint(Bh[k8 + quad    ][cB]);
                bh[nf][1] = __float_as_uint(Bh[k8 + quad + 4][cB]);
                bl[nf][0] = __float_as_uint(Bl[k8 + quad    ][cB]);
                bl[nf][1] = __float_as_uint(Bl[k8 + quad + 4][cB]);
            }
            #pragma unroll
            for (int mf = 0; mf < 4; mf++)
                #pragma unroll
                for (int nf = 0; nf < 4; nf++) {
                    mma_tf32(acc[mf][nf], al[mf][0], al[mf][1], al[mf][2], al[mf][3],
                             bh[nf][0], bh[nf][1]);
                    mma_tf32(acc[mf][nf], ah[mf][0], ah[mf][1], ah[mf][2], ah[mf][3],
                             bl[nf][0], bl[nf][1]);
                    mma_tf32(acc[mf][nf], ah[mf][0], ah[mf][1], ah[mf][2], ah[mf][3],
                             bh[nf][0], bh[nf][1]);
                }
        }
        __syncthreads();
    }

    // ---- epilogue ----
    float s0[4], q0[4], s1[4], q1[4];
    #pragma unroll
    for (int nf = 0; nf < 4; nf++) { s0[nf] = q0[nf] = s1[nf] = q1[nf] = 0.f; }

    #pragma unroll
    for (int mf = 0; mf < 4; mf++) {
        int r0 = row0 + wm * 64 + mf * 16 + grp;
        int r1 = r0 + 8;
        #pragma unroll
        for (int nf = 0; nf < 4; nf++) {
            int cc = col0 + wn * 32 + nf * 8 + quad * 2;
            float b0 = bias[cc], b1 = bias[cc + 1];
            float v00 = acc[mf][nf][0] + b0, v01 = acc[mf][nf][1] + b1;
            float v10 = acc[mf][nf][2] + b0, v11 = acc[mf][nf][3] + b1;
            if (MODE != 0) {
                v00 = fmaxf(v00, 0.f); v01 = fmaxf(v01, 0.f);
                v10 = fmaxf(v10, 0.f); v11 = fmaxf(v11, 0.f);
            }
            if (r0 < M) {
                *(float2*)&C[(size_t)r0 * NC + cc] = make_float2(v00, v01);
                if (MODE == 0) { s0[nf] += v00; q0[nf] += v00 * v00;
                                 s1[nf] += v01; q1[nf] += v01 * v01; }
            }
            if (r1 < M) {
                *(float2*)&C[(size_t)r1 * NC + cc] = make_float2(v10, v11);
                if (MODE == 0) { s0[nf] += v10; q0[nf] += v10 * v10;
                                 s1[nf] += v11; q1[nf] += v11 * v11; }
            }
        }
    }
    if (MODE == 0) {
        #pragma unroll
        for (int nf = 0; nf < 4; nf++) {
            #pragma unroll
            for (int off = 16; off >= 4; off >>= 1) {
                s0[nf] += __shfl_xor_sync(0xffffffff, s0[nf], off);
                q0[nf] += __shfl_xor_sync(0xffffffff, q0[nf], off);
                s1[nf] += __shfl_xor_sync(0xffffffff, s1[nf], off);
                q1[nf] += __shfl_xor_sync(0xffffffff, q1[nf], off);
            }
        }
        if (grp == 0) {
            #pragma unroll
            for (int nf = 0; nf < 4; nf++) {
                int cc = col0 + wn * 32 + nf * 8 + quad * 2;
                atomicAdd(&colstats[cc],          s0[nf]);
                atomicAdd(&colstats[cc + 1],      s1[nf]);
                atomicAdd(&colstats[DH + cc],     q0[nf]);
                atomicAdd(&colstats[DH + cc + 1], q1[nf]);
            }
        }
    }
}

// ---------------- BN finalize ----------------
__global__ void bn_finalize_k(const float* __restrict__ g, const float* __restrict__ be,
                              int M, int statoff) {
    int j = threadIdx.x;
    if (j >= DH) return;
    float mu = d_colstats[statoff + j] / (float)M;
    float var = d_colstats[statoff + DH + j] / (float)M - mu * mu;
    float sc = g[j] * rsqrtf(var + 1e-5f);
    d_scale[j] = sc;
    d_shift[j] = be[j] - mu * sc;
}

// ---------------- pooling: one block (512 thr) per graph, 4-way rows -------
__global__ void pool_k(const float* __restrict__ h, int off_sum, int off_max) {
    __shared__ float ssum[4][128];
    __shared__ float smax[4][128];
    int gph = blockIdx.x;
    int j = threadIdx.x & 127;
    int part = threadIdx.x >> 7;   // 0..3
    int s = d_gstart[gph], e = d_gend[gph];
    float sum = 0.f, mx = 0.f;
    for (int r = s + part; r < e; r += 4) {
        float v = h[(size_t)r * DH + j];
        sum += v; mx = fmaxf(mx, v);
    }
    ssum[part][j] = sum;
    smax[part][j] = mx;
    __syncthreads();
    if (part == 0) {
        sum = ssum[0][j] + ssum[1][j] + ssum[2][j] + ssum[3][j];
        mx = fmaxf(fmaxf(smax[0][j], smax[1][j]), fmaxf(smax[2][j], smax[3][j]));
        d_pool[(size_t)gph * 512 + off_sum + j] = sum;
        d_pool[(size_t)gph * 512 + off_max + j] = mx;
    }
}

// ---------------- final linear + sigmoid ----------------
__global__ void final_k(const float* __restrict__ r1, const float* __restrict__ w,
                        const float* __restrict__ b, float* __restrict__ out, int out_size) {
    int gph = blockIdx.x;
    int tid = threadIdx.x;   // 128
    float s = 0.f;
    #pragma unroll
    for (int k = tid; k < 512; k += 128) s += r1[(size_t)gph * 512 + k] * w[k];
    __shared__ float red[128];
    red[tid] = s;
    __syncthreads();
    for (int st = 64; st > 0; st >>= 1) {
        if (tid < st) red[tid] += red[tid + st];
        __syncthreads();
    }
    if (tid == 0) {
        float h = red[0] + b[0];
        float sg = 1.f / (1.f + expf(-h));
        out[gph] = sg;
        if (out_size >= 2 * GG) out[GG + gph] = h;
    }
}

// ---------------- host launch ----------------
extern "C" void kernel_launch(void* const* d_in, const int* in_sizes, int n_in,
                              void* d_out, int out_size) {
    const float* x      = (const float*)d_in[0];
    const void*  edge   = d_in[1];
    const void*  batch  = d_in[2];
    const float* c1_W1  = (const float*)d_in[3];
    const float* c1_b1  = (const float*)d_in[4];
    const float* c1_g   = (const float*)d_in[5];
    const float* c1_be  = (const float*)d_in[6];
    const float* c1_W2  = (const float*)d_in[7];
    const float* c1_b2  = (const float*)d_in[8];
    const float* c2_W1  = (const float*)d_in[9];
    const float* c2_b1  = (const float*)d_in[10];
    const float* c2_g   = (const float*)d_in[11];
    const float* c2_be  = (const float*)d_in[12];
    const float* c2_W2  = (const float*)d_in[13];
    const float* c2_b2  = (const float*)d_in[14];
    const float* lin1_W = (const float*)d_in[15];
    const float* lin1_b = (const float*)d_in[16];
    const float* lin2_W = (const float*)d_in[17];
    const float* lin2_b = (const float*)d_in[18];

    const int N = in_sizes[0] / DH;       // 50000
    const int E = in_sizes[1] / 2;        // 600000
    float* out = (float*)d_out;

    float *agg, *hpre, *h1, *h2, *pool, *r1, *colstats, *sc, *sh;
    cudaGetSymbolAddress((void**)&agg,      d_agg);
    cudaGetSymbolAddress((void**)&hpre,     d_hpre);
    cudaGetSymbolAddress((void**)&h1,       d_h1);
    cudaGetSymbolAddress((void**)&h2,       d_h2);
    cudaGetSymbolAddress((void**)&pool,     d_pool);
    cudaGetSymbolAddress((void**)&r1,       d_r1);
    cudaGetSymbolAddress((void**)&colstats, d_colstats);
    cudaGetSymbolAddress((void**)&sc,       d_scale);
    cudaGetSymbolAddress((void**)&sh,       d_shift);

    // 1) index dtype detection + conversion
    detect_k<<<1, 256>>>(edge, batch, 2 * E, N, (long long)N, (long long)GG);
    convert_k<<<(2 * E + N + 255) / 256, 256>>>(edge, batch, E, N);

    // 2) per-graph segment bounds (batch sorted) via binary search
    bounds_k<<<2, 256>>>(N);

    // 3) zero colstats (both convs' buffers at once)
    zero_k<<<1, 128>>>(colstats, DH);   // 4*DH floats = DH float4s

    const int gemm_gx = (N + 127) / 128;
    const dim3 gemm_grid(gemm_gx, 1);
    const int scat_blocks = (E * 32 + 255) / 256;

    // ---- conv1 ----
    zero_k<<<1024, 256>>>(agg, N * DH / 4);
    scatter_k<<<scat_blocks, 256>>>(x, agg, E);
    gemm_tc<0><<<gemm_grid, 256>>>(agg, x, c1_W1, c1_b1, hpre, N, DH, DH,
                                   nullptr, nullptr, colstats);
    bn_finalize_k<<<1, DH>>>(c1_g, c1_be, N, 0);
    gemm_tc<1><<<gemm_grid, 256>>>(hpre, nullptr, c1_W2, c1_b2, h1, N, DH, DH,
                                   sc, sh, nullptr);
    pool_k<<<GG, 512>>>(h1, 0, 256);

    // ---- conv2 ----
    zero_k<<<1024, 256>>>(agg, N * DH / 4);
    scatter_k<<<scat_blocks, 256>>>(h1, agg, E);
    gemm_tc<0><<<gemm_grid, 256>>>(agg, h1, c2_W1, c2_b1, hpre, N, DH, DH,
                                   nullptr, nullptr, colstats + 2 * DH);
    bn_finalize_k<<<1, DH>>>(c2_g, c2_be, N, 2 * DH);
    gemm_tc<1><<<gemm_grid, 256>>>(hpre, nullptr, c2_W2, c2_b2, h2, N, DH, DH,
                                   sc, sh, nullptr);
    pool_k<<<GG, 512>>>(h2, 128, 384);

    // ---- readout ----
    {
        dim3 grid((GG + 127) / 128, 4);   // M=512, NC=512
        gemm_tc<2><<<grid, 256>>>(pool, nullptr, lin1_W, lin1_b, r1, GG, 512, 512,
                                  nullptr, nullptr, nullptr);
    }
    final_k<<<GG, 128>>>(r1, lin2_W, lin2_b, out, out_size);
}